// round 10
// baseline (speedup 1.0000x reference)
#include <cuda_runtime.h>
#include <cuda_bf16.h>

#define IMG_H 480
#define IMG_W 640
#define HW (IMG_H * IMG_W)          // 307200
#define CHW (3 * HW)
#define QPP (HW / 4)                // float4 quads per plane = 76800
#define THREADS 256
#define MUPB 300                    // main units per batch (256 quads each)
#define RUPB 75                     // reduce units per batch (1024 quads, 4/thr)
#define CB 8                        // batches per chunk (30 MB -> L2-hot)
#define NBLK 740                    // 148 SMs x 5 blocks, residency guaranteed
#define MAX_B 64

// Device scratch (per harness rules). g_sum starts zeroed (static init) and is
// re-zeroed by block 0 after the final barrier each run -> replay-safe.
// Barrier generation counter is monotonic across replays by design.
__device__ float g_sum[MAX_B];
__device__ unsigned g_bar_count = 0;
__device__ unsigned g_bar_gen = 0;

// Generation-based grid barrier. All NBLK blocks are guaranteed resident
// (launch_bounds(256,5) => <=51 regs => 5 blocks/SM; 148*5 = 740).
// tid0's preceding atomics/stores are ordered by the leading threadfence.
__device__ __forceinline__ void grid_barrier(int tid) {
    __syncthreads();
    if (tid == 0) {
        __threadfence();
        const unsigned my_gen = atomicAdd(&g_bar_gen, 0u);
        const unsigned ticket = atomicAdd(&g_bar_count, 1u);
        if (ticket == NBLK - 1u) {
            g_bar_count = 0u;
            __threadfence();
            atomicAdd(&g_bar_gen, 1u);
        } else {
            while (atomicAdd(&g_bar_gen, 0u) == my_gen) { __nanosleep(64); }
        }
        __threadfence();
    }
    __syncthreads();
}

__device__ __forceinline__ float quad_gray(const float4& r4, const float4& g4,
                                           const float4& b4, float B) {
    float s = 0.0f;
    float r, g, bl;
    #define ACC(comp) \
        r = __saturatef(r4.comp * B); \
        g = __saturatef(g4.comp * B); \
        bl = __saturatef(b4.comp * B); \
        s += 0.299f * r + 0.587f * g + 0.114f * bl;
    ACC(x) ACC(y) ACC(z) ACC(w)
    #undef ACC
    return s;
}

// One reduce unit: 1024 quads of batch b, 4 quads/thread, block-reduced,
// single atomicAdd by tid0. Default-cached loads -> chunk becomes L2-hot for
// the NEXT segment's main units. Called uniformly by all threads of a block.
__device__ __forceinline__ void reduce_unit(const float* __restrict__ x,
                                            const float* __restrict__ bf,
                                            int b, int unit, int tid,
                                            float* warp_s) {
    const float4* base = (const float4*)(x + (size_t)b * CHW);
    const float B = __ldg(&bf[b]);
    const int q0 = unit * (THREADS * 4) + tid;

    float s;
    {
        const int qa = q0, qb = q0 + THREADS;
        float4 r0 = base[qa], g0 = base[qa + QPP], c0 = base[qa + 2 * QPP];
        float4 r1 = base[qb], g1 = base[qb + QPP], c1 = base[qb + 2 * QPP];
        s = quad_gray(r0, g0, c0, B) + quad_gray(r1, g1, c1, B);
    }
    {
        const int qa = q0 + 2 * THREADS, qb = q0 + 3 * THREADS;
        float4 r0 = base[qa], g0 = base[qa + QPP], c0 = base[qa + 2 * QPP];
        float4 r1 = base[qb], g1 = base[qb + QPP], c1 = base[qb + 2 * QPP];
        s += quad_gray(r0, g0, c0, B) + quad_gray(r1, g1, c1, B);
    }

    #pragma unroll
    for (int o = 16; o > 0; o >>= 1)
        s += __shfl_xor_sync(0xFFFFFFFFu, s, o);

    const int lane = tid & 31;
    const int wid = tid >> 5;
    if (lane == 0) warp_s[wid] = s;
    __syncthreads();
    if (tid == 0) {
        float t = warp_s[0];
        #pragma unroll
        for (int w = 1; w < THREADS / 32; w++) t += warp_s[w];
        atomicAdd(&g_sum[b], t);
    }
    __syncthreads();
}

// Branchless fused per-pixel pipeline (validated in R5-R7):
// v*s == chroma identically; hue ramps with mod-6 eliminated.
__device__ __forceinline__ void process_px(float& r, float& g, float& b,
                                           float Bf, float Cf, float cm,
                                           float Sf, float hfv) {
    r = __saturatef(r * Bf);
    g = __saturatef(g * Bf);
    b = __saturatef(b * Bf);
    r = __saturatef(fmaf(Cf, r, cm));
    g = __saturatef(fmaf(Cf, g, cm));
    b = __saturatef(fmaf(Cf, b, cm));
    const float gray = 0.299f * r + 0.587f * g + 0.114f * b;
    const float sm = (1.0f - Sf) * gray;
    r = __saturatef(fmaf(Sf, r, sm));
    g = __saturatef(fmaf(Sf, g, sm));
    b = __saturatef(fmaf(Sf, b, sm));
    const float maxc = fmaxf(r, fmaxf(g, b));
    const float minc = fminf(r, fminf(g, b));
    const float c = maxc - minc;
    const float crd = (c == 0.0f) ? 1.0f : c;
    float num, base;
    if (maxc == r)      { num = g - b; base = 0.0f; }   // priority order kept
    else if (maxc == g) { num = b - r; base = 2.0f; }
    else                { num = r - g; base = 4.0f; }
    float h = (base + __fdividef(num, crd)) * (1.0f / 6.0f);
    h -= floorf(h);
    h += hfv;
    h -= floorf(h);
    const float i6 = h * 6.0f;
    const float wr = fminf(i6 - 1.0f, 5.0f - i6);
    const float wg = fmaxf(1.0f - i6, i6 - 3.0f);
    const float wb = fmaxf(3.0f - i6, i6 - 5.0f);
    r = fmaf(-c, __saturatef(wr), maxc);
    g = fmaf(-c, __saturatef(wg), maxc);
    b = fmaf(-c, __saturatef(wb), maxc);
}

// One main unit: 256 quads of batch b. Reads are L2-hot (chunk was reduced in
// the previous segment); __ldcs marks last-touch, __stcs streams the output.
// Mean read via __ldcg (L2-only) -- avoids stale-L1 on the g_sum line.
__device__ __forceinline__ void main_unit(const float* __restrict__ x,
                                          const float* __restrict__ bf,
                                          const float* __restrict__ cf,
                                          const float* __restrict__ sf,
                                          const float* __restrict__ hf,
                                          float* __restrict__ out,
                                          int b, int unit, int tid) {
    const int quad = unit * THREADS + tid;
    const float4* inb = (const float4*)(x + (size_t)b * CHW);
    float4* outb = (float4*)(out + (size_t)b * CHW);

    const float B = __ldg(&bf[b]);
    const float C = __ldg(&cf[b]);
    const float S = __ldg(&sf[b]);
    const float Hf = __ldg(&hf[b]);
    const float m = __ldcg(&g_sum[b]) * (1.0f / (float)HW);
    const float cm = (1.0f - C) * m;

    float4 r4 = __ldcs(&inb[quad]);
    float4 g4 = __ldcs(&inb[quad + QPP]);
    float4 b4 = __ldcs(&inb[quad + 2 * QPP]);

    process_px(r4.x, g4.x, b4.x, B, C, cm, S, Hf);
    process_px(r4.y, g4.y, b4.y, B, C, cm, S, Hf);
    process_px(r4.z, g4.z, b4.z, B, C, cm, S, Hf);
    process_px(r4.w, g4.w, b4.w, B, C, cm, S, Hf);

    __stcs(&outb[quad],           r4);
    __stcs(&outb[quad + QPP],     g4);
    __stcs(&outb[quad + 2 * QPP], b4);
}

// Persistent pipeline: segment s does [main chunk s-1] + [reduce chunk s],
// grid barrier between segments. Chunk = 8 batches = 30 MB, so every main
// read hits L2 (loaded by the reduce in the previous segment).
__global__ void __launch_bounds__(THREADS, 5)
cr_persist_kernel(const float* __restrict__ x,
                  const float* __restrict__ bf, const float* __restrict__ cf,
                  const float* __restrict__ sf, const float* __restrict__ hf,
                  float* __restrict__ out, int nb) {
    const int tid = threadIdx.x;
    __shared__ float warp_s[THREADS / 32];

    const int nchunk = (nb + CB - 1) / CB;

    for (int s = 0; s <= nchunk; s++) {
        int mBase = 0, mB = 0, rBase = 0, rB = 0;
        if (s > 0) {
            mBase = (s - 1) * CB;
            mB = (nb - mBase < CB) ? (nb - mBase) : CB;
        }
        if (s < nchunk) {
            rBase = s * CB;
            rB = (nb - rBase < CB) ? (nb - rBase) : CB;
        }
        const int mUnits = mB * MUPB;
        const int rUnits = rB * RUPB;
        const int tot = mUnits + rUnits;

        // u is block-uniform -> the __syncthreads inside reduce_unit is safe.
        for (int u = blockIdx.x; u < tot; u += NBLK) {
            if (u < mUnits) {
                const int bl = u / MUPB;
                const int un = u - bl * MUPB;
                main_unit(x, bf, cf, sf, hf, out, mBase + bl, un, tid);
            } else {
                const int v = u - mUnits;
                const int bl = v / RUPB;
                const int un = v - bl * RUPB;
                reduce_unit(x, bf, rBase + bl, un, tid, warp_s);
            }
        }
        grid_barrier(tid);
    }

    // All means consumed (final barrier passed) -> reset for the next replay.
    if (blockIdx.x == 0 && tid < MAX_B) g_sum[tid] = 0.0f;
}

extern "C" void kernel_launch(void* const* d_in, const int* in_sizes, int n_in,
                              void* d_out, int out_size) {
    const float* x  = (const float*)d_in[0];
    const float* bf = (const float*)d_in[1];
    const float* cf = (const float*)d_in[2];
    const float* sf = (const float*)d_in[3];
    const float* hf = (const float*)d_in[4];
    float* out = (float*)d_out;

    const int nb = out_size / CHW;  // num_samples is 1 by shape constraints

    cr_persist_kernel<<<NBLK, THREADS>>>(x, bf, cf, sf, hf, out, nb);
}

// round 11
// speedup vs baseline: 1.2561x; 1.2561x over previous
#include <cuda_runtime.h>
#include <cuda_bf16.h>

#define IMG_H 480
#define IMG_W 640
#define HW (IMG_H * IMG_W)          // 307200
#define CHW (3 * HW)
#define QPP (HW / 4)                // float4 quads per plane = 76800
#define RED_THREADS 256
#define RED_QPT 4
#define RED_BLOCKS_PER_PLANE (QPP / (RED_THREADS * RED_QPT))   // 75, exact
#define MAIN_THREADS 256
#define MAIN_BLOCKS_PER_PLANE (QPP / MAIN_THREADS)             // 300, exact
#define CHUNK_B 16                  // 16 batches = 59 MB -> L2-hot across launch
#define MAX_B 64

// Scratch (device globals per harness rules).
// g_graysum starts zeroed (static init); the LAST main block across ALL
// chunks (global ticket) re-zeroes it after every mean has been consumed.
__device__ float g_graysum[MAX_B];
__device__ unsigned g_fin = 0;

__device__ __forceinline__ float quad_gray(const float4& r4, const float4& g4,
                                           const float4& b4, float B) {
    float s = 0.0f;
    float r, g, bl;
    #define ACC(comp) \
        r = __saturatef(r4.comp * B); \
        g = __saturatef(g4.comp * B); \
        bl = __saturatef(b4.comp * B); \
        s += 0.299f * r + 0.587f * g + 0.114f * bl;
    ACC(x) ACC(y) ACC(z) ACC(w)
    #undef ACC
    return s;
}

// Reduce one chunk: grid (75, chunk_nb), batch offset b0. Default-cached
// loads leave the chunk L2-resident for the immediately following main chunk
// (L2 persists across kernel launches; only L1D is flushed).
__global__ void __launch_bounds__(RED_THREADS)
cr_reduce_kernel(const float* __restrict__ x, const float* __restrict__ bf,
                 int b0) {
    const int b = b0 + blockIdx.y;
    const int q0 = blockIdx.x * (RED_THREADS * RED_QPT) + threadIdx.x;
    const float4* base = (const float4*)(x + (size_t)b * CHW);
    const float B = bf[b];

    float s;
    {   // half 1 (6 loads in flight)
        const int qa = q0, qb = q0 + RED_THREADS;
        float4 r0 = base[qa], g0 = base[qa + QPP], c0 = base[qa + 2 * QPP];
        float4 r1 = base[qb], g1 = base[qb + QPP], c1 = base[qb + 2 * QPP];
        s = quad_gray(r0, g0, c0, B) + quad_gray(r1, g1, c1, B);
    }
    {   // half 2
        const int qa = q0 + 2 * RED_THREADS, qb = q0 + 3 * RED_THREADS;
        float4 r0 = base[qa], g0 = base[qa + QPP], c0 = base[qa + 2 * QPP];
        float4 r1 = base[qb], g1 = base[qb + QPP], c1 = base[qb + 2 * QPP];
        s += quad_gray(r0, g0, c0, B) + quad_gray(r1, g1, c1, B);
    }

    #pragma unroll
    for (int o = 16; o > 0; o >>= 1)
        s += __shfl_xor_sync(0xFFFFFFFFu, s, o);

    __shared__ float warp_s[RED_THREADS / 32];
    const int lane = threadIdx.x & 31;
    const int wid = threadIdx.x >> 5;
    if (lane == 0) warp_s[wid] = s;
    __syncthreads();
    if (wid == 0) {
        s = (lane < RED_THREADS / 32) ? warp_s[lane] : 0.0f;
        #pragma unroll
        for (int o = 4; o > 0; o >>= 1)
            s += __shfl_xor_sync(0xFFFFFFFFu, s, o);
        if (lane == 0) atomicAdd(&g_graysum[b], s);
    }
}

// Branchless fused pipeline (validated R5-R7). cm = (1-C)*mean hoisted;
// v*s == chroma identically; hue ramps with mod-6 algebraically eliminated.
__device__ __forceinline__ void process_px(float& r, float& g, float& b,
                                           float Bf, float Cf, float cm,
                                           float Sf, float hfv) {
    r = __saturatef(r * Bf);
    g = __saturatef(g * Bf);
    b = __saturatef(b * Bf);
    r = __saturatef(fmaf(Cf, r, cm));
    g = __saturatef(fmaf(Cf, g, cm));
    b = __saturatef(fmaf(Cf, b, cm));
    const float gray = 0.299f * r + 0.587f * g + 0.114f * b;
    const float sm = (1.0f - Sf) * gray;
    r = __saturatef(fmaf(Sf, r, sm));
    g = __saturatef(fmaf(Sf, g, sm));
    b = __saturatef(fmaf(Sf, b, sm));
    const float maxc = fmaxf(r, fmaxf(g, b));
    const float minc = fminf(r, fminf(g, b));
    const float c = maxc - minc;
    const float crd = (c == 0.0f) ? 1.0f : c;
    float num, base;
    if (maxc == r)      { num = g - b; base = 0.0f; }   // priority order kept
    else if (maxc == g) { num = b - r; base = 2.0f; }
    else                { num = r - g; base = 4.0f; }
    float h = (base + __fdividef(num, crd)) * (1.0f / 6.0f);
    h -= floorf(h);          // positive mod 1 (jnp semantics)
    h += hfv;
    h -= floorf(h);
    const float i6 = h * 6.0f;               // in [0, 6]
    const float wr = fminf(i6 - 1.0f, 5.0f - i6);
    const float wg = fmaxf(1.0f - i6, i6 - 3.0f);
    const float wb = fmaxf(3.0f - i6, i6 - 5.0f);
    r = fmaf(-c, __saturatef(wr), maxc);
    g = fmaf(-c, __saturatef(wg), maxc);
    b = fmaf(-c, __saturatef(wb), maxc);
}

// Main pass for one chunk: grid (300, chunk_nb), batch offset b0. Reads hit
// the L2-resident chunk left by the preceding reduce launch; __ldcs marks
// last-touch, __stcs streams output. Mean broadcast via shared memory; the
// barrier drains the STS so the load completes before this block's GLOBAL
// ticket — the very last main block (across all chunks) resets g_graysum.
__global__ void __launch_bounds__(MAIN_THREADS)
cr_main_kernel(const float* __restrict__ x,
               const float* __restrict__ bf, const float* __restrict__ cf,
               const float* __restrict__ sf, const float* __restrict__ hf,
               float* __restrict__ out, int b0, unsigned total_blocks) {
    const int b = b0 + blockIdx.y;
    const int quad = blockIdx.x * MAIN_THREADS + threadIdx.x;

    __shared__ float sh_m;
    if (threadIdx.x == 0) sh_m = g_graysum[b];
    __syncthreads();     // BAR drains the STS → load completed before ticket
    if (threadIdx.x == 0) {
        const unsigned ticket = atomicAdd(&g_fin, 1u);
        if (ticket == total_blocks - 1u) {
            #pragma unroll
            for (int i = 0; i < MAX_B; i++) g_graysum[i] = 0.0f;
            g_fin = 0u;
            __threadfence();
        }
    }
    const float m = sh_m * (1.0f / (float)HW);

    const float4* inb = (const float4*)(x + (size_t)b * CHW);
    float4* outb = (float4*)(out + (size_t)b * CHW);

    const float B = bf[b];
    const float C = cf[b];
    const float S = sf[b];
    const float Hf = hf[b];
    const float cm = (1.0f - C) * m;

    float4 r4 = __ldcs(&inb[quad]);
    float4 g4 = __ldcs(&inb[quad + QPP]);
    float4 b4 = __ldcs(&inb[quad + 2 * QPP]);

    process_px(r4.x, g4.x, b4.x, B, C, cm, S, Hf);
    process_px(r4.y, g4.y, b4.y, B, C, cm, S, Hf);
    process_px(r4.z, g4.z, b4.z, B, C, cm, S, Hf);
    process_px(r4.w, g4.w, b4.w, B, C, cm, S, Hf);

    __stcs(&outb[quad],           r4);
    __stcs(&outb[quad + QPP],     g4);
    __stcs(&outb[quad + 2 * QPP], b4);
}

extern "C" void kernel_launch(void* const* d_in, const int* in_sizes, int n_in,
                              void* d_out, int out_size) {
    const float* x  = (const float*)d_in[0];
    const float* bf = (const float*)d_in[1];
    const float* cf = (const float*)d_in[2];
    const float* sf = (const float*)d_in[3];
    const float* hf = (const float*)d_in[4];
    float* out = (float*)d_out;

    const int nb = out_size / CHW;  // num_samples is 1 by shape constraints
    const unsigned total_main_blocks = (unsigned)(MAIN_BLOCKS_PER_PLANE * nb);

    // Chunked pairs: reduce(chunk) then main(chunk). The launch boundary is
    // the barrier; L2 carries the chunk between the two kernels.
    for (int b0 = 0; b0 < nb; b0 += CHUNK_B) {
        const int cb = (nb - b0 < CHUNK_B) ? (nb - b0) : CHUNK_B;

        dim3 rgrid(RED_BLOCKS_PER_PLANE, cb);
        cr_reduce_kernel<<<rgrid, RED_THREADS>>>(x, bf, b0);

        dim3 mgrid(MAIN_BLOCKS_PER_PLANE, cb);
        cr_main_kernel<<<mgrid, MAIN_THREADS>>>(x, bf, cf, sf, hf, out,
                                                b0, total_main_blocks);
    }
}